// round 8
// baseline (speedup 1.0000x reference)
#include <cuda_runtime.h>
#include <cuda_bf16.h>
#include <math.h>
#include <stdint.h>

#define B_  2
#define H_  8
#define T_  2048
#define KD  128
#define BH  (B_*H_)
#define BN  32
#define NKT (T_/BN)      // 64 kv tiles of 32
#define QT64 (T_/64)     // 32 q tiles of 64 rows
#define NTASK (BH*QT64)  // 512
#define NELEM (BH*T_*KD)
#define GRID_MAIN 444

// ---------------- device-global scratch (no runtime alloc allowed) --------
__device__ float d_g [BH*T_];
__device__ float d_cm[BH*T_];
__device__ float d_nf[BH*T_];
__device__ float d_ce[BH*T_];
__device__ float d_Gt[BH*NKT];
__device__ unsigned int d_task_ctr;

__device__ __nv_bfloat16 d_kh[NELEM], d_kl[NELEM];
__device__ __nv_bfloat16 d_vh[NELEM], d_vl[NELEM];

// ---------------- helpers -------------------------------------------------
__device__ __forceinline__ uint32_t smem_u32(const void* p) {
    uint32_t a;
    asm("{ .reg .u64 t; cvta.to.shared.u64 t, %1; cvt.u32.u64 %0, t; }"
        : "=r"(a) : "l"(p));
    return a;
}

#define CP16(dst, src) \
    asm volatile("cp.async.cg.shared.global [%0], [%1], 16;" :: "r"(dst), "l"(src))
#define CP_COMMIT() asm volatile("cp.async.commit_group;" ::: "memory")
#define CP_WAIT0()  asm volatile("cp.async.wait_group 0;" ::: "memory")

__device__ __forceinline__ void ldm_x4(uint32_t* r, uint32_t addr) {
    asm volatile("ldmatrix.sync.aligned.m8n8.x4.shared.b16 {%0,%1,%2,%3}, [%4];"
        : "=r"(r[0]), "=r"(r[1]), "=r"(r[2]), "=r"(r[3]) : "r"(addr));
}
__device__ __forceinline__ void ldm_x4_t(uint32_t* r, uint32_t addr) {
    asm volatile("ldmatrix.sync.aligned.m8n8.x4.trans.shared.b16 {%0,%1,%2,%3}, [%4];"
        : "=r"(r[0]), "=r"(r[1]), "=r"(r[2]), "=r"(r[3]) : "r"(addr));
}
__device__ __forceinline__ void mma16816(float (&d)[4], const uint32_t (&a)[4],
                                         uint32_t b0, uint32_t b1) {
    asm volatile(
        "mma.sync.aligned.m16n8k16.row.col.f32.bf16.bf16.f32 "
        "{%0,%1,%2,%3}, {%4,%5,%6,%7}, {%8,%9}, {%0,%1,%2,%3};"
        : "+f"(d[0]), "+f"(d[1]), "+f"(d[2]), "+f"(d[3])
        : "r"(a[0]), "r"(a[1]), "r"(a[2]), "r"(a[3]), "r"(b0), "r"(b1));
}

// fast split: hi = truncate-to-bf16, lo = RN(x - hi) (exact complement)
__device__ __forceinline__ void split2f(float a, float b, uint32_t& h, uint32_t& l) {
    uint32_t ua = __float_as_uint(a) & 0xffff0000u;
    uint32_t ub = __float_as_uint(b) & 0xffff0000u;
    float la = a - __uint_as_float(ua);
    float lb = b - __uint_as_float(ub);
    h = (ua >> 16) | ub;
    __nv_bfloat162 p = __float22bfloat162_rn(make_float2(la, lb));
    l = *reinterpret_cast<uint32_t*>(&p);
}

// swizzled chunk offset within a plane: 16 chunks (16B each) per 256B row
__device__ __forceinline__ uint32_t swzo(int row, int ck) {
    return (uint32_t)((row * 16 + (ck ^ (row & 7))) << 4);
}

// ---------------- smem layout (bytes, per CTA) -----------------------------
#define OFF_TILE(b) ((b) * 32768)
#define P_KH 0
#define P_KL 8192
#define P_VH 16384
#define P_VL 24576
#define OFF_CE(b) (65536 + (b) * 128)
#define OFF_G(b)  (65792 + (b) * 128)
#define SMEM_TOTAL 66048
// Q staging (before mainloop, reuses buffer area): QH at 0, QL at 16384

// ---------------------------------------------------------------------------
// Fused pre-pass. Blocks [0,16): per-head gate scan (launched FIRST so they
// overlap the splat blocks instead of trailing them). Blocks [16, 4112):
// split K/V into bf16 planes. Block 0 resets the work queue.
// ---------------------------------------------------------------------------
__global__ void fused_pre(const float* __restrict__ k, const float* __restrict__ v,
                          const float* __restrict__ ig, const float* __restrict__ fg) {
    __shared__ double sh[256];
    __shared__ float shf[256];
    __shared__ float tm[64];
    const int tid = threadIdx.x;

    if (blockIdx.x >= 16) {
        int i = (blockIdx.x - 16) * 256 + tid;   // one float4 each
        float4 kv = ((const float4*)k)[i];
        float4 vv = ((const float4*)v)[i];
        uint32_t h0, l0, h1, l1;
        split2f(kv.x, kv.y, h0, l0); split2f(kv.z, kv.w, h1, l1);
        ((uint2*)d_kh)[i] = make_uint2(h0, h1);
        ((uint2*)d_kl)[i] = make_uint2(l0, l1);
        split2f(vv.x, vv.y, h0, l0); split2f(vv.z, vv.w, h1, l1);
        ((uint2*)d_vh)[i] = make_uint2(h0, h1);
        ((uint2*)d_vl)[i] = make_uint2(l0, l1);
        return;
    }

    const int bh = blockIdx.x;
    if (bh == 0 && tid == 0) d_task_ctr = GRID_MAIN;
    const float* fp = fg + (size_t)bh * T_;
    const float* ip = ig + (size_t)bh * T_;
    const int base = tid * 8;

    double lf[8]; float gi[8];
#pragma unroll
    for (int r = 0; r < 8; r++) {
        float x = fp[base + r];
        lf[r] = (double)(fminf(x, 0.f) - log1pf(__expf(-fabsf(x))));
        gi[r] = ip[base + r];
    }
    double run = 0.0, fc[8];
#pragma unroll
    for (int r = 0; r < 8; r++) { run += lf[r]; fc[r] = run; }

    sh[tid] = run; __syncthreads();
    for (int off = 1; off < 256; off <<= 1) {
        double t = 0.0; if (tid >= off) t = sh[tid - off];
        __syncthreads();
        if (tid >= off) sh[tid] += t;
        __syncthreads();
    }
    double addoff = sh[tid] - run;

    double g[8], gm[8], runm = -1e300;
#pragma unroll
    for (int r = 0; r < 8; r++) {
        fc[r] += addoff;
        g[r]  = (double)gi[r] - fc[r];
        runm  = fmax(runm, g[r]);
        gm[r] = runm;
    }
    __syncthreads();
    sh[tid] = runm; __syncthreads();
    for (int off = 1; off < 256; off <<= 1) {
        double t = -1e300; if (tid >= off) t = sh[tid - off];
        __syncthreads();
        if (tid >= off) sh[tid] = fmax(sh[tid], t);
        __syncthreads();
    }
    double prevmax = (tid == 0) ? -1e300 : sh[tid - 1];

    float gf[8];
#pragma unroll
    for (int r = 0; r < 8; r++) {
        double cm = fmax(prevmax, gm[r]);
        gf[r] = (float)g[r];
        d_g [bh*T_ + base + r] = gf[r];
        d_cm[bh*T_ + base + r] = (float)cm;
        d_nf[bh*T_ + base + r] = __expf((float)(-(fc[r] + cm)));
    }

    // per-32-element kv-tile max of g (tile = 4 consecutive threads)
    float lmax = gf[0];
#pragma unroll
    for (int r = 1; r < 8; r++) lmax = fmaxf(lmax, gf[r]);
    __syncthreads();
    shf[tid] = lmax; __syncthreads();
    if (tid < 64) {
        float mx = shf[tid * 4];
#pragma unroll
        for (int u = 1; u < 4; u++) mx = fmaxf(mx, shf[tid * 4 + u]);
        tm[tid] = mx;
        d_Gt[bh*NKT + tid] = mx;
    }
    __syncthreads();
    float G = tm[tid >> 2];
#pragma unroll
    for (int r = 0; r < 8; r++)
        d_ce[bh*T_ + base + r] = __expf(gf[r] - G);
}

// ---------------------------------------------------------------------------
// tile loader (K/V bf16 planes + per-tile aux vectors) via cp.async
// ---------------------------------------------------------------------------
__device__ __forceinline__ void load_tile(uint32_t sb, int b, int bh, int kt, int tid) {
    size_t gbase = ((size_t)(bh * T_ + kt * BN)) * KD;
    const char* gkh = (const char*)d_kh + gbase * 2;
    const char* gkl = (const char*)d_kl + gbase * 2;
    const char* gvh = (const char*)d_vh + gbase * 2;
    const char* gvl = (const char*)d_vl + gbase * 2;
    uint32_t tb = sb + OFF_TILE(b);
#pragma unroll
    for (int u = 0; u < 4; u++) {
        int ch = tid + u * 128;            // 0..511
        int r = ch >> 4, c = ch & 15;
        uint32_t a = swzo(r, c);
        size_t go = (size_t)ch * 16;
        CP16(tb + P_KH + a, gkh + go);
        CP16(tb + P_KL + a, gkl + go);
        CP16(tb + P_VH + a, gvh + go);
        CP16(tb + P_VL + a, gvl + go);
    }
    if (tid < 8) {
        CP16(sb + OFF_CE(b) + tid * 16,
             (const char*)(d_ce + bh * T_ + kt * BN) + tid * 16);
    } else if (tid < 16) {
        CP16(sb + OFF_G(b) + (tid - 8) * 16,
             (const char*)(d_g + bh * T_ + kt * BN) + (tid - 8) * 16);
    }
}

// ---------------------------------------------------------------------------
// Main kernel: 128 threads (4 warps), BM=64, BN=32, 3 CTAs/SM (12 warps),
// double-buffered 32KB tiles, 1 sync/iter, persistent atomic work queue.
// ---------------------------------------------------------------------------
__global__ void __launch_bounds__(128, 3)
mlstm_mma(const float* __restrict__ q, float* __restrict__ out) {
    extern __shared__ char smem[];
    __shared__ int sh_task;
    const uint32_t sb = smem_u32(smem);
    const int tid  = threadIdx.x;
    const int lane = tid & 31;
    const int wid  = tid >> 5;
    const int m0   = wid * 16;
    const float scale = 0.08838834764831845f; // 128^-0.5

    int task = blockIdx.x;                 // wave-1 seed; queue continues at 444
    for (;;) {
        if (task >= NTASK) return;
        const int bh = task & 15;
        const int qt = (QT64 - 1) - (task >> 4);   // descending work
        const int NT = 2 * qt + 2;
        const int q0 = qt * 64;

        // ---- stage Q (scaled, split) into buffer area, then frags -> regs ----
        const float* qbase = q + (size_t)(bh * T_ + q0) * KD;
#pragma unroll
        for (int u = 0; u < 8; u++) {
            int ch = tid + u * 128;            // 0..1023
            int r = ch >> 4, c = ch & 15;
            const float4* src = (const float4*)(qbase + r * 128 + c * 8);
            float4 x0 = src[0], x1 = src[1];
            uint32_t h0, l0, h1, l1, h2, l2, h3, l3;
            split2f(x0.x * scale, x0.y * scale, h0, l0);
            split2f(x0.z * scale, x0.w * scale, h1, l1);
            split2f(x1.x * scale, x1.y * scale, h2, l2);
            split2f(x1.z * scale, x1.w * scale, h3, l3);
            uint32_t a = swzo(r, c);
            *(uint4*)(smem + 0     + a) = make_uint4(h0, h1, h2, h3);
            *(uint4*)(smem + 16384 + a) = make_uint4(l0, l1, l2, l3);
        }
        __syncthreads();

        uint32_t qh[8][4], ql[8][4];
#pragma unroll
        for (int kb = 0; kb < 8; kb++) {
            int row = m0 + (lane & 15);
            int ck  = 2 * kb + (lane >> 4);
            ldm_x4(qh[kb], sb + 0     + swzo(row, ck));
            ldm_x4(ql[kb], sb + 16384 + swzo(row, ck));
        }
        __syncthreads();   // frags in regs; buffer 0 may be overwritten now

        load_tile(sb, 0, bh, 0, tid);
        CP_COMMIT();

        const int rowg0 = q0 + m0 + (lane >> 2);
        const int rowg1 = rowg0 + 8;
        const float cm0 = d_cm[bh * T_ + rowg0];
        const float cm1 = d_cm[bh * T_ + rowg1];
        const float nf0 = d_nf[bh * T_ + rowg0];
        const float nf1 = d_nf[bh * T_ + rowg1];

        float hacc[16][4];
#pragma unroll
        for (int i = 0; i < 16; i++)
#pragma unroll
            for (int j = 0; j < 4; j++) hacc[i][j] = 0.f;
        float rs0 = 0.f, rs1 = 0.f;

        CP_WAIT0();
        __syncthreads();

        for (int kt = 0; kt < NT; kt++) {
            const int b = kt & 1;
            if (kt + 1 < NT) { load_tile(sb, 1 - b, bh, kt + 1, tid); CP_COMMIT(); }
            const uint32_t tb = sb + OFF_TILE(b);
            const float Gtv = __ldg(&d_Gt[bh * NKT + kt]);

            const int  smin = kt * BN;
            const int  wmrow = q0 + m0;                       // warp's min row
            const bool fullmask = (smin > wmrow + 15);        // tile fully masked
            const bool partial  = !fullmask && (smin + BN - 1 > wmrow);

            if (!fullmask) {
                // ---- S = Qs . K^T (3 bf16 chains) ----
                float sa[4][4];
#pragma unroll
                for (int i = 0; i < 4; i++)
#pragma unroll
                    for (int j = 0; j < 4; j++) sa[i][j] = 0.f;

#pragma unroll
                for (int kb = 0; kb < 8; kb++) {
#pragma unroll
                    for (int np = 0; np < 2; np++) {
                        uint32_t bh4[4], bl4[4];
                        {
                            int row = 16 * np + (lane & 7) + ((lane >> 4) << 3);
                            int ck  = 2 * kb + ((lane >> 3) & 1);
                            ldm_x4(bh4, tb + P_KH + swzo(row, ck));
                            ldm_x4(bl4, tb + P_KL + swzo(row, ck));
                        }
                        mma16816(sa[2*np],   qh[kb], bh4[0], bh4[1]);
                        mma16816(sa[2*np+1], qh[kb], bh4[2], bh4[3]);
                        mma16816(sa[2*np],   ql[kb], bh4[0], bh4[1]);
                        mma16816(sa[2*np+1], ql[kb], bh4[2], bh4[3]);
                        mma16816(sa[2*np],   qh[kb], bl4[0], bl4[1]);
                        mma16816(sa[2*np+1], qh[kb], bl4[2], bl4[3]);
                    }
                }

                // ---- decay + rowsum + split P into A fragments ----
                const float* ce = (const float*)(smem + OFF_CE(b));
                const float* gg = (const float*)(smem + OFF_G(b));
                const float rr0 = __expf(Gtv - cm0);
                const float rr1 = __expf(Gtv - cm1);
                uint32_t phf[2][4], plf[2][4];
#pragma unroll
                for (int nb = 0; nb < 4; nb++) {
                    int n0 = 8 * nb + 2 * (lane & 3);
                    float p0, p1, p2, p3;
                    if (!partial) {
                        float c0 = ce[n0], c1 = ce[n0 + 1];
                        p0 = sa[nb][0] * rr0 * c0; p1 = sa[nb][1] * rr0 * c1;
                        p2 = sa[nb][2] * rr1 * c0; p3 = sa[nb][3] * rr1 * c1;
                    } else {
                        int s0g = smin + n0;
                        float g0 = gg[n0], g1 = gg[n0 + 1];
                        p0 = (s0g     <= rowg0) ? sa[nb][0] * __expf(g0 - cm0) : 0.f;
                        p1 = (s0g + 1 <= rowg0) ? sa[nb][1] * __expf(g1 - cm0) : 0.f;
                        p2 = (s0g     <= rowg1) ? sa[nb][2] * __expf(g0 - cm1) : 0.f;
                        p3 = (s0g + 1 <= rowg1) ? sa[nb][3] * __expf(g1 - cm1) : 0.f;
                    }
                    rs0 += p0 + p1; rs1 += p2 + p3;
                    int kf = nb >> 1, hx = (nb & 1) * 2;
                    split2f(p0, p1, phf[kf][hx],     plf[kf][hx]);
                    split2f(p2, p3, phf[kf][hx + 1], plf[kf][hx + 1]);
                }

                // ---- H += P . V (3 bf16 chains) ----
#pragma unroll
                for (int kf = 0; kf < 2; kf++) {
#pragma unroll
                    for (int np = 0; np < 8; np++) {
                        uint32_t vh4[4], vl4[4];
                        {
                            int row = 16 * kf + (lane & 7) + (((lane >> 3) & 1) << 3);
                            int ck  = 2 * np + (lane >> 4);
                            ldm_x4_t(vh4, tb + P_VH + swzo(row, ck));
                            ldm_x4_t(vl4, tb + P_VL + swzo(row, ck));
                        }
                        mma16816(hacc[2*np],   phf[kf], vh4[0], vh4[1]);
                        mma16816(hacc[2*np+1], phf[kf], vh4[2], vh4[3]);
                        mma16816(hacc[2*np],   phf[kf], vl4[0], vl4[1]);
                        mma16816(hacc[2*np+1], phf[kf], vl4[2], vl4[3]);
                        mma16816(hacc[2*np],   plf[kf], vh4[0], vh4[1]);
                        mma16816(hacc[2*np+1], plf[kf], vh4[2], vh4[3]);
                    }
                }
            }

            CP_WAIT0();
            __syncthreads();
        }

        // ---- reduce rowsums, normalize, write ----
        rs0 += __shfl_xor_sync(0xffffffffu, rs0, 1);
        rs0 += __shfl_xor_sync(0xffffffffu, rs0, 2);
        rs1 += __shfl_xor_sync(0xffffffffu, rs1, 1);
        rs1 += __shfl_xor_sync(0xffffffffu, rs1, 2);
        const float inv0 = 1.f / fmaxf(fabsf(rs0), nf0);
        const float inv1 = 1.f / fmaxf(fabsf(rs1), nf1);
        float* o0 = out + ((size_t)(bh * T_ + rowg0)) * KD;
        float* o1 = out + ((size_t)(bh * T_ + rowg1)) * KD;
#pragma unroll
        for (int nb = 0; nb < 16; nb++) {
            int c = 8 * nb + 2 * (lane & 3);
            *(float2*)(o0 + c) = make_float2(hacc[nb][0] * inv0, hacc[nb][1] * inv0);
            *(float2*)(o1 + c) = make_float2(hacc[nb][2] * inv1, hacc[nb][3] * inv1);
        }

        // ---- next task from queue ----
        if (tid == 0) sh_task = (int)atomicAdd(&d_task_ctr, 1u);
        __syncthreads();
        task = sh_task;
    }
}

// ---------------------------------------------------------------------------
extern "C" void kernel_launch(void* const* d_in, const int* in_sizes, int n_in,
                              void* d_out, int out_size) {
    const float* q  = (const float*)d_in[0];
    const float* k  = (const float*)d_in[1];
    const float* v  = (const float*)d_in[2];
    const float* ig = (const float*)d_in[3];
    const float* fg = (const float*)d_in[4];
    float* out = (float*)d_out;

    fused_pre<<<4096 + 16, 256>>>(k, v, ig, fg);

    cudaFuncSetAttribute(mlstm_mma,
                         cudaFuncAttributeMaxDynamicSharedMemorySize, SMEM_TOTAL);
    mlstm_mma<<<GRID_MAIN, 128, SMEM_TOTAL>>>(q, out);
}

// round 9
// speedup vs baseline: 1.0003x; 1.0003x over previous
#include <cuda_runtime.h>
#include <cuda_bf16.h>
#include <math.h>
#include <stdint.h>

#define B_  2
#define H_  8
#define T_  2048
#define KD  128
#define BH  (B_*H_)
#define BN  32
#define NKT (T_/BN)      // 64 kv tiles of 32
#define QT64 (T_/64)     // 32 q tiles of 64 rows
#define NTASK (BH*QT64)  // 512
#define NELEM (BH*T_*KD)
#define GRID_MAIN 444

// ---------------- device-global scratch (no runtime alloc allowed) --------
__device__ float d_g [BH*T_];
__device__ float d_cm[BH*T_];
__device__ float d_nf[BH*T_];
__device__ float d_ce[BH*T_];
__device__ float d_Gt[BH*NKT];
__device__ unsigned int d_task_ctr;

__device__ __nv_bfloat16 d_kh[NELEM], d_kl[NELEM];
__device__ __nv_bfloat16 d_vh[NELEM], d_vl[NELEM];

// ---------------- helpers -------------------------------------------------
__device__ __forceinline__ uint32_t smem_u32(const void* p) {
    uint32_t a;
    asm("{ .reg .u64 t; cvta.to.shared.u64 t, %1; cvt.u32.u64 %0, t; }"
        : "=r"(a) : "l"(p));
    return a;
}

#define CP16(dst, src) \
    asm volatile("cp.async.cg.shared.global [%0], [%1], 16;" :: "r"(dst), "l"(src))
#define CP_COMMIT() asm volatile("cp.async.commit_group;" ::: "memory")
#define CP_WAIT0()  asm volatile("cp.async.wait_group 0;" ::: "memory")

__device__ __forceinline__ void ldm_x4(uint32_t* r, uint32_t addr) {
    asm volatile("ldmatrix.sync.aligned.m8n8.x4.shared.b16 {%0,%1,%2,%3}, [%4];"
        : "=r"(r[0]), "=r"(r[1]), "=r"(r[2]), "=r"(r[3]) : "r"(addr));
}
__device__ __forceinline__ void ldm_x4_t(uint32_t* r, uint32_t addr) {
    asm volatile("ldmatrix.sync.aligned.m8n8.x4.trans.shared.b16 {%0,%1,%2,%3}, [%4];"
        : "=r"(r[0]), "=r"(r[1]), "=r"(r[2]), "=r"(r[3]) : "r"(addr));
}
__device__ __forceinline__ void mma16816(float (&d)[4], const uint32_t (&a)[4],
                                         uint32_t b0, uint32_t b1) {
    asm volatile(
        "mma.sync.aligned.m16n8k16.row.col.f32.bf16.bf16.f32 "
        "{%0,%1,%2,%3}, {%4,%5,%6,%7}, {%8,%9}, {%0,%1,%2,%3};"
        : "+f"(d[0]), "+f"(d[1]), "+f"(d[2]), "+f"(d[3])
        : "r"(a[0]), "r"(a[1]), "r"(a[2]), "r"(a[3]), "r"(b0), "r"(b1));
}

// fast split: hi = truncate-to-bf16, lo = RN(x - hi) (exact complement)
__device__ __forceinline__ void split2f(float a, float b, uint32_t& h, uint32_t& l) {
    uint32_t ua = __float_as_uint(a) & 0xffff0000u;
    uint32_t ub = __float_as_uint(b) & 0xffff0000u;
    float la = a - __uint_as_float(ua);
    float lb = b - __uint_as_float(ub);
    h = (ua >> 16) | ub;
    __nv_bfloat162 p = __float22bfloat162_rn(make_float2(la, lb));
    l = *reinterpret_cast<uint32_t*>(&p);
}

// swizzled chunk offset within a plane: 16 chunks (16B each) per 256B row
__device__ __forceinline__ uint32_t swzo(int row, int ck) {
    return (uint32_t)((row * 16 + (ck ^ (row & 7))) << 4);
}

// ---------------- smem layout (bytes, per CTA) -----------------------------
#define OFF_TILE(b) ((b) * 32768)
#define P_KH 0
#define P_KL 8192
#define P_VH 16384
#define P_VL 24576
#define OFF_CE(b) (65536 + (b) * 128)
#define OFF_G(b)  (65792 + (b) * 128)
#define SMEM_TOTAL 66048
// Q staging (before mainloop, reuses buffer area): QH at 0, QL at 16384

// ---------------------------------------------------------------------------
// Fused pre-pass. Blocks [0,16): per-head gate scan (launched FIRST so they
// overlap the splat blocks instead of trailing them). Blocks [16, 4112):
// split K/V into bf16 planes. Block 0 resets the work queue.
// ---------------------------------------------------------------------------
__global__ void fused_pre(const float* __restrict__ k, const float* __restrict__ v,
                          const float* __restrict__ ig, const float* __restrict__ fg) {
    __shared__ double sh[256];
    __shared__ float shf[256];
    __shared__ float tm[64];
    const int tid = threadIdx.x;

    if (blockIdx.x >= 16) {
        int i = (blockIdx.x - 16) * 256 + tid;   // one float4 each
        float4 kv = ((const float4*)k)[i];
        float4 vv = ((const float4*)v)[i];
        uint32_t h0, l0, h1, l1;
        split2f(kv.x, kv.y, h0, l0); split2f(kv.z, kv.w, h1, l1);
        ((uint2*)d_kh)[i] = make_uint2(h0, h1);
        ((uint2*)d_kl)[i] = make_uint2(l0, l1);
        split2f(vv.x, vv.y, h0, l0); split2f(vv.z, vv.w, h1, l1);
        ((uint2*)d_vh)[i] = make_uint2(h0, h1);
        ((uint2*)d_vl)[i] = make_uint2(l0, l1);
        return;
    }

    const int bh = blockIdx.x;
    if (bh == 0 && tid == 0) d_task_ctr = GRID_MAIN;
    const float* fp = fg + (size_t)bh * T_;
    const float* ip = ig + (size_t)bh * T_;
    const int base = tid * 8;

    double lf[8]; float gi[8];
#pragma unroll
    for (int r = 0; r < 8; r++) {
        float x = fp[base + r];
        lf[r] = (double)(fminf(x, 0.f) - log1pf(__expf(-fabsf(x))));
        gi[r] = ip[base + r];
    }
    double run = 0.0, fc[8];
#pragma unroll
    for (int r = 0; r < 8; r++) { run += lf[r]; fc[r] = run; }

    sh[tid] = run; __syncthreads();
    for (int off = 1; off < 256; off <<= 1) {
        double t = 0.0; if (tid >= off) t = sh[tid - off];
        __syncthreads();
        if (tid >= off) sh[tid] += t;
        __syncthreads();
    }
    double addoff = sh[tid] - run;

    double g[8], gm[8], runm = -1e300;
#pragma unroll
    for (int r = 0; r < 8; r++) {
        fc[r] += addoff;
        g[r]  = (double)gi[r] - fc[r];
        runm  = fmax(runm, g[r]);
        gm[r] = runm;
    }
    __syncthreads();
    sh[tid] = runm; __syncthreads();
    for (int off = 1; off < 256; off <<= 1) {
        double t = -1e300; if (tid >= off) t = sh[tid - off];
        __syncthreads();
        if (tid >= off) sh[tid] = fmax(sh[tid], t);
        __syncthreads();
    }
    double prevmax = (tid == 0) ? -1e300 : sh[tid - 1];

    float gf[8];
#pragma unroll
    for (int r = 0; r < 8; r++) {
        double cm = fmax(prevmax, gm[r]);
        gf[r] = (float)g[r];
        d_g [bh*T_ + base + r] = gf[r];
        d_cm[bh*T_ + base + r] = (float)cm;
        d_nf[bh*T_ + base + r] = __expf((float)(-(fc[r] + cm)));
    }

    // per-32-element kv-tile max of g (tile = 4 consecutive threads)
    float lmax = gf[0];
#pragma unroll
    for (int r = 1; r < 8; r++) lmax = fmaxf(lmax, gf[r]);
    __syncthreads();
    shf[tid] = lmax; __syncthreads();
    if (tid < 64) {
        float mx = shf[tid * 4];
#pragma unroll
        for (int u = 1; u < 4; u++) mx = fmaxf(mx, shf[tid * 4 + u]);
        tm[tid] = mx;
        d_Gt[bh*NKT + tid] = mx;
    }
    __syncthreads();
    float G = tm[tid >> 2];
#pragma unroll
    for (int r = 0; r < 8; r++)
        d_ce[bh*T_ + base + r] = __expf(gf[r] - G);
}

// ---------------------------------------------------------------------------
// tile loader (K/V bf16 planes + per-tile aux vectors) via cp.async
// ---------------------------------------------------------------------------
__device__ __forceinline__ void load_tile(uint32_t sb, int b, int bh, int kt, int tid) {
    size_t gbase = ((size_t)(bh * T_ + kt * BN)) * KD;
    const char* gkh = (const char*)d_kh + gbase * 2;
    const char* gkl = (const char*)d_kl + gbase * 2;
    const char* gvh = (const char*)d_vh + gbase * 2;
    const char* gvl = (const char*)d_vl + gbase * 2;
    uint32_t tb = sb + OFF_TILE(b);
#pragma unroll
    for (int u = 0; u < 4; u++) {
        int ch = tid + u * 128;            // 0..511
        int r = ch >> 4, c = ch & 15;
        uint32_t a = swzo(r, c);
        size_t go = (size_t)ch * 16;
        CP16(tb + P_KH + a, gkh + go);
        CP16(tb + P_KL + a, gkl + go);
        CP16(tb + P_VH + a, gvh + go);
        CP16(tb + P_VL + a, gvl + go);
    }
    if (tid < 8) {
        CP16(sb + OFF_CE(b) + tid * 16,
             (const char*)(d_ce + bh * T_ + kt * BN) + tid * 16);
    } else if (tid < 16) {
        CP16(sb + OFF_G(b) + (tid - 8) * 16,
             (const char*)(d_g + bh * T_ + kt * BN) + (tid - 8) * 16);
    }
}

// ---------------------------------------------------------------------------
// Main kernel: 128 threads (4 warps), BM=64, BN=32, 3 CTAs/SM (12 warps),
// double-buffered 32KB tiles, 1 sync/iter, persistent atomic work queue.
// ---------------------------------------------------------------------------
__global__ void __launch_bounds__(128, 3)
mlstm_mma(const float* __restrict__ q, float* __restrict__ out) {
    extern __shared__ char smem[];
    __shared__ int sh_task;
    const uint32_t sb = smem_u32(smem);
    const int tid  = threadIdx.x;
    const int lane = tid & 31;
    const int wid  = tid >> 5;
    const int m0   = wid * 16;
    const float scale = 0.08838834764831845f; // 128^-0.5

    int task = blockIdx.x;                 // wave-1 seed; queue continues at 444
    for (;;) {
        if (task >= NTASK) return;
        const int bh = task & 15;
        const int qt = (QT64 - 1) - (task >> 4);   // descending work
        const int NT = 2 * qt + 2;
        const int q0 = qt * 64;

        // ---- stage Q (scaled, split) into buffer area, then frags -> regs ----
        const float* qbase = q + (size_t)(bh * T_ + q0) * KD;
#pragma unroll
        for (int u = 0; u < 8; u++) {
            int ch = tid + u * 128;            // 0..1023
            int r = ch >> 4, c = ch & 15;
            const float4* src = (const float4*)(qbase + r * 128 + c * 8);
            float4 x0 = src[0], x1 = src[1];
            uint32_t h0, l0, h1, l1, h2, l2, h3, l3;
            split2f(x0.x * scale, x0.y * scale, h0, l0);
            split2f(x0.z * scale, x0.w * scale, h1, l1);
            split2f(x1.x * scale, x1.y * scale, h2, l2);
            split2f(x1.z * scale, x1.w * scale, h3, l3);
            uint32_t a = swzo(r, c);
            *(uint4*)(smem + 0     + a) = make_uint4(h0, h1, h2, h3);
            *(uint4*)(smem + 16384 + a) = make_uint4(l0, l1, l2, l3);
        }
        __syncthreads();

        uint32_t qh[8][4], ql[8][4];
#pragma unroll
        for (int kb = 0; kb < 8; kb++) {
            int row = m0 + (lane & 15);
            int ck  = 2 * kb + (lane >> 4);
            ldm_x4(qh[kb], sb + 0     + swzo(row, ck));
            ldm_x4(ql[kb], sb + 16384 + swzo(row, ck));
        }
        __syncthreads();   // frags in regs; buffer 0 may be overwritten now

        load_tile(sb, 0, bh, 0, tid);
        CP_COMMIT();

        const int rowg0 = q0 + m0 + (lane >> 2);
        const int rowg1 = rowg0 + 8;
        const float cm0 = d_cm[bh * T_ + rowg0];
        const float cm1 = d_cm[bh * T_ + rowg1];
        const float nf0 = d_nf[bh * T_ + rowg0];
        const float nf1 = d_nf[bh * T_ + rowg1];

        float hacc[16][4];
#pragma unroll
        for (int i = 0; i < 16; i++)
#pragma unroll
            for (int j = 0; j < 4; j++) hacc[i][j] = 0.f;
        float rs0 = 0.f, rs1 = 0.f;

        CP_WAIT0();
        __syncthreads();

        for (int kt = 0; kt < NT; kt++) {
            const int b = kt & 1;
            if (kt + 1 < NT) { load_tile(sb, 1 - b, bh, kt + 1, tid); CP_COMMIT(); }
            const uint32_t tb = sb + OFF_TILE(b);
            const float Gtv = __ldg(&d_Gt[bh * NKT + kt]);

            const int  smin = kt * BN;
            const int  wmrow = q0 + m0;                       // warp's min row
            const bool fullmask = (smin > wmrow + 15);        // tile fully masked
            const bool partial  = !fullmask && (smin + BN - 1 > wmrow);

            if (!fullmask) {
                // ---- S = Qs . K^T (3 bf16 chains) ----
                float sa[4][4];
#pragma unroll
                for (int i = 0; i < 4; i++)
#pragma unroll
                    for (int j = 0; j < 4; j++) sa[i][j] = 0.f;

#pragma unroll
                for (int kb = 0; kb < 8; kb++) {
#pragma unroll
                    for (int np = 0; np < 2; np++) {
                        uint32_t bh4[4], bl4[4];
                        {
                            int row = 16 * np + (lane & 7) + ((lane >> 4) << 3);
                            int ck  = 2 * kb + ((lane >> 3) & 1);
                            ldm_x4(bh4, tb + P_KH + swzo(row, ck));
                            ldm_x4(bl4, tb + P_KL + swzo(row, ck));
                        }
                        mma16816(sa[2*np],   qh[kb], bh4[0], bh4[1]);
                        mma16816(sa[2*np+1], qh[kb], bh4[2], bh4[3]);
                        mma16816(sa[2*np],   ql[kb], bh4[0], bh4[1]);
                        mma16816(sa[2*np+1], ql[kb], bh4[2], bh4[3]);
                        mma16816(sa[2*np],   qh[kb], bl4[0], bl4[1]);
                        mma16816(sa[2*np+1], qh[kb], bl4[2], bl4[3]);
                    }
                }

                // ---- decay + rowsum + split P into A fragments ----
                const float* ce = (const float*)(smem + OFF_CE(b));
                const float* gg = (const float*)(smem + OFF_G(b));
                const float rr0 = __expf(Gtv - cm0);
                const float rr1 = __expf(Gtv - cm1);
                uint32_t phf[2][4], plf[2][4];
#pragma unroll
                for (int nb = 0; nb < 4; nb++) {
                    int n0 = 8 * nb + 2 * (lane & 3);
                    float p0, p1, p2, p3;
                    if (!partial) {
                        float c0 = ce[n0], c1 = ce[n0 + 1];
                        p0 = sa[nb][0] * rr0 * c0; p1 = sa[nb][1] * rr0 * c1;
                        p2 = sa[nb][2] * rr1 * c0; p3 = sa[nb][3] * rr1 * c1;
                    } else {
                        int s0g = smin + n0;
                        float g0 = gg[n0], g1 = gg[n0 + 1];
                        p0 = (s0g     <= rowg0) ? sa[nb][0] * __expf(g0 - cm0) : 0.f;
                        p1 = (s0g + 1 <= rowg0) ? sa[nb][1] * __expf(g1 - cm0) : 0.f;
                        p2 = (s0g     <= rowg1) ? sa[nb][2] * __expf(g0 - cm1) : 0.f;
                        p3 = (s0g + 1 <= rowg1) ? sa[nb][3] * __expf(g1 - cm1) : 0.f;
                    }
                    rs0 += p0 + p1; rs1 += p2 + p3;
                    int kf = nb >> 1, hx = (nb & 1) * 2;
                    split2f(p0, p1, phf[kf][hx],     plf[kf][hx]);
                    split2f(p2, p3, phf[kf][hx + 1], plf[kf][hx + 1]);
                }

                // ---- H += P . V (3 bf16 chains) ----
#pragma unroll
                for (int kf = 0; kf < 2; kf++) {
#pragma unroll
                    for (int np = 0; np < 8; np++) {
                        uint32_t vh4[4], vl4[4];
                        {
                            int row = 16 * kf + (lane & 7) + (((lane >> 3) & 1) << 3);
                            int ck  = 2 * np + (lane >> 4);
                            ldm_x4_t(vh4, tb + P_VH + swzo(row, ck));
                            ldm_x4_t(vl4, tb + P_VL + swzo(row, ck));
                        }
                        mma16816(hacc[2*np],   phf[kf], vh4[0], vh4[1]);
                        mma16816(hacc[2*np+1], phf[kf], vh4[2], vh4[3]);
                        mma16816(hacc[2*np],   phf[kf], vl4[0], vl4[1]);
                        mma16816(hacc[2*np+1], phf[kf], vl4[2], vl4[3]);
                        mma16816(hacc[2*np],   plf[kf], vh4[0], vh4[1]);
                        mma16816(hacc[2*np+1], plf[kf], vh4[2], vh4[3]);
                    }
                }
            }

            CP_WAIT0();
            __syncthreads();
        }

        // ---- reduce rowsums, normalize, write ----
        rs0 += __shfl_xor_sync(0xffffffffu, rs0, 1);
        rs0 += __shfl_xor_sync(0xffffffffu, rs0, 2);
        rs1 += __shfl_xor_sync(0xffffffffu, rs1, 1);
        rs1 += __shfl_xor_sync(0xffffffffu, rs1, 2);
        const float inv0 = 1.f / fmaxf(fabsf(rs0), nf0);
        const float inv1 = 1.f / fmaxf(fabsf(rs1), nf1);
        float* o0 = out + ((size_t)(bh * T_ + rowg0)) * KD;
        float* o1 = out + ((size_t)(bh * T_ + rowg1)) * KD;
#pragma unroll
        for (int nb = 0; nb < 16; nb++) {
            int c = 8 * nb + 2 * (lane & 3);
            *(float2*)(o0 + c) = make_float2(hacc[nb][0] * inv0, hacc[nb][1] * inv0);
            *(float2*)(o1 + c) = make_float2(hacc[nb][2] * inv1, hacc[nb][3] * inv1);
        }

        // ---- next task from queue ----
        if (tid == 0) sh_task = (int)atomicAdd(&d_task_ctr, 1u);
        __syncthreads();
        task = sh_task;
    }
}

// ---------------------------------------------------------------------------
extern "C" void kernel_launch(void* const* d_in, const int* in_sizes, int n_in,
                              void* d_out, int out_size) {
    const float* q  = (const float*)d_in[0];
    const float* k  = (const float*)d_in[1];
    const float* v  = (const float*)d_in[2];
    const float* ig = (const float*)d_in[3];
    const float* fg = (const float*)d_in[4];
    float* out = (float*)d_out;

    fused_pre<<<4096 + 16, 256>>>(k, v, ig, fg);

    cudaFuncSetAttribute(mlstm_mma,
                         cudaFuncAttributeMaxDynamicSharedMemorySize, SMEM_TOTAL);
    mlstm_mma<<<GRID_MAIN, 128, SMEM_TOTAL>>>(q, out);
}

// round 10
// speedup vs baseline: 1.3521x; 1.3518x over previous
#include <cuda_runtime.h>
#include <cuda_bf16.h>
#include <math.h>
#include <stdint.h>

#define B_  2
#define H_  8
#define T_  2048
#define KD  128
#define BH  (B_*H_)
#define BN  64
#define NKT (T_/BN)      // 32 kv tiles of 64
#define NQT (T_/128)     // 16 q tiles of 128
#define NTASK (BH*NQT)   // 256
#define NELEM (BH*T_*KD)
#define GRID_MAIN 148

// ---------------- device-global scratch -----------------------------------
__device__ float d_g [BH*T_];
__device__ float d_cm[BH*T_];
__device__ float d_nf[BH*T_];
__device__ float d_ce[BH*T_];
__device__ float d_Gt[BH*NKT];
__device__ unsigned int d_task_ctr;

__device__ __nv_bfloat16 d_kh[NELEM], d_kl[NELEM];
__device__ __nv_bfloat16 d_vh[NELEM], d_vl[NELEM];

// ---------------- helpers -------------------------------------------------
__device__ __forceinline__ uint32_t smem_u32(const void* p) {
    uint32_t a;
    asm("{ .reg .u64 t; cvta.to.shared.u64 t, %1; cvt.u32.u64 %0, t; }"
        : "=r"(a) : "l"(p));
    return a;
}

#define CP16(dst, src) \
    asm volatile("cp.async.cg.shared.global [%0], [%1], 16;" :: "r"(dst), "l"(src))
#define CP_COMMIT() asm volatile("cp.async.commit_group;" ::: "memory")
#define CP_WAIT0()  asm volatile("cp.async.wait_group 0;" ::: "memory")

__device__ __forceinline__ void ldm_x4(uint32_t* r, uint32_t addr) {
    asm volatile("ldmatrix.sync.aligned.m8n8.x4.shared.b16 {%0,%1,%2,%3}, [%4];"
        : "=r"(r[0]), "=r"(r[1]), "=r"(r[2]), "=r"(r[3]) : "r"(addr));
}
__device__ __forceinline__ void ldm_x4_t(uint32_t* r, uint32_t addr) {
    asm volatile("ldmatrix.sync.aligned.m8n8.x4.trans.shared.b16 {%0,%1,%2,%3}, [%4];"
        : "=r"(r[0]), "=r"(r[1]), "=r"(r[2]), "=r"(r[3]) : "r"(addr));
}
__device__ __forceinline__ void mma16816(float (&d)[4], const uint32_t (&a)[4],
                                         uint32_t b0, uint32_t b1) {
    asm volatile(
        "mma.sync.aligned.m16n8k16.row.col.f32.bf16.bf16.f32 "
        "{%0,%1,%2,%3}, {%4,%5,%6,%7}, {%8,%9}, {%0,%1,%2,%3};"
        : "+f"(d[0]), "+f"(d[1]), "+f"(d[2]), "+f"(d[3])
        : "r"(a[0]), "r"(a[1]), "r"(a[2]), "r"(a[3]), "r"(b0), "r"(b1));
}

// fast split: hi = truncate-to-bf16, lo = RN(x - hi)
__device__ __forceinline__ void split2f(float a, float b, uint32_t& h, uint32_t& l) {
    uint32_t ua = __float_as_uint(a) & 0xffff0000u;
    uint32_t ub = __float_as_uint(b) & 0xffff0000u;
    float la = a - __uint_as_float(ua);
    float lb = b - __uint_as_float(ub);
    h = (ua >> 16) | ub;
    __nv_bfloat162 p = __float22bfloat162_rn(make_float2(la, lb));
    l = *reinterpret_cast<uint32_t*>(&p);
}

// swizzled chunk offset: 16 chunks (16B) per 256B row
__device__ __forceinline__ uint32_t swzo(int row, int ck) {
    return (uint32_t)((row * 16 + (ck ^ (row & 7))) << 4);
}

// ---------------- smem layout (bytes) -------------------------------------
#define OFF_QH   0
#define OFF_QL   32768
#define OFF_TILE(b) (65536 + (b) * 65536)
#define P_KH 0
#define P_KL 16384
#define P_VH 32768
#define P_VL 49152
#define OFF_CE(b) (196608 + (b) * 256)
#define OFF_G(b)  (197120 + (b) * 256)
#define SMEM_TOTAL 197632

// ---------------------------------------------------------------------------
// Fused pre-pass. Blocks [0,16): per-head gate scan (FIRST, so they overlap
// the splat wave). Blocks [16,4112): split K/V into bf16 hi/lo planes.
// ---------------------------------------------------------------------------
__global__ void fused_pre(const float* __restrict__ k, const float* __restrict__ v,
                          const float* __restrict__ ig, const float* __restrict__ fg) {
    __shared__ double sh[256];
    __shared__ float shf[256];
    __shared__ float tm[32];
    const int tid = threadIdx.x;

    if (blockIdx.x >= 16) {
        int i = (blockIdx.x - 16) * 256 + tid;   // one float4 each
        float4 kv = ((const float4*)k)[i];
        float4 vv = ((const float4*)v)[i];
        uint32_t h0, l0, h1, l1;
        split2f(kv.x, kv.y, h0, l0); split2f(kv.z, kv.w, h1, l1);
        ((uint2*)d_kh)[i] = make_uint2(h0, h1);
        ((uint2*)d_kl)[i] = make_uint2(l0, l1);
        split2f(vv.x, vv.y, h0, l0); split2f(vv.z, vv.w, h1, l1);
        ((uint2*)d_vh)[i] = make_uint2(h0, h1);
        ((uint2*)d_vl)[i] = make_uint2(l0, l1);
        return;
    }

    const int bh = blockIdx.x;
    if (bh == 0 && tid == 0) d_task_ctr = GRID_MAIN;
    const float* fp = fg + (size_t)bh * T_;
    const float* ip = ig + (size_t)bh * T_;
    const int base = tid * 8;

    double lf[8]; float gi[8];
#pragma unroll
    for (int r = 0; r < 8; r++) {
        float x = fp[base + r];
        lf[r] = (double)(fminf(x, 0.f) - log1pf(__expf(-fabsf(x))));
        gi[r] = ip[base + r];
    }
    double run = 0.0, fc[8];
#pragma unroll
    for (int r = 0; r < 8; r++) { run += lf[r]; fc[r] = run; }

    sh[tid] = run; __syncthreads();
    for (int off = 1; off < 256; off <<= 1) {
        double t = 0.0; if (tid >= off) t = sh[tid - off];
        __syncthreads();
        if (tid >= off) sh[tid] += t;
        __syncthreads();
    }
    double addoff = sh[tid] - run;

    double g[8], gm[8], runm = -1e300;
#pragma unroll
    for (int r = 0; r < 8; r++) {
        fc[r] += addoff;
        g[r]  = (double)gi[r] - fc[r];
        runm  = fmax(runm, g[r]);
        gm[r] = runm;
    }
    __syncthreads();
    sh[tid] = runm; __syncthreads();
    for (int off = 1; off < 256; off <<= 1) {
        double t = -1e300; if (tid >= off) t = sh[tid - off];
        __syncthreads();
        if (tid >= off) sh[tid] = fmax(sh[tid], t);
        __syncthreads();
    }
    double prevmax = (tid == 0) ? -1e300 : sh[tid - 1];

    float gf[8];
#pragma unroll
    for (int r = 0; r < 8; r++) {
        double cm = fmax(prevmax, gm[r]);
        gf[r] = (float)g[r];
        d_g [bh*T_ + base + r] = gf[r];
        d_cm[bh*T_ + base + r] = (float)cm;
        d_nf[bh*T_ + base + r] = __expf((float)(-(fc[r] + cm)));
    }

    // per-64-element kv-tile max of g (tile = 8 consecutive threads)
    float lmax = gf[0];
#pragma unroll
    for (int r = 1; r < 8; r++) lmax = fmaxf(lmax, gf[r]);
    __syncthreads();
    shf[tid] = lmax; __syncthreads();
    if (tid < 32) {
        float mx = shf[tid * 8];
#pragma unroll
        for (int u = 1; u < 8; u++) mx = fmaxf(mx, shf[tid * 8 + u]);
        tm[tid] = mx;
        d_Gt[bh*NKT + tid] = mx;
    }
    __syncthreads();
    float G = tm[tid >> 3];
#pragma unroll
    for (int r = 0; r < 8; r++)
        d_ce[bh*T_ + base + r] = __expf(gf[r] - G);
}

// ---------------------------------------------------------------------------
// tile loader: 64-row K/V bf16 planes + aux vectors, cp.async, 256 threads
// ---------------------------------------------------------------------------
__device__ __forceinline__ void load_tile(uint32_t sb, int b, int bh, int kt, int tid) {
    size_t gbase = ((size_t)(bh * T_ + kt * BN)) * KD;
    const char* gkh = (const char*)d_kh + gbase * 2;
    const char* gkl = (const char*)d_kl + gbase * 2;
    const char* gvh = (const char*)d_vh + gbase * 2;
    const char* gvl = (const char*)d_vl + gbase * 2;
    uint32_t tb = sb + OFF_TILE(b);
#pragma unroll
    for (int u = 0; u < 4; u++) {
        int ch = tid + u * 256;            // 0..1023
        int r = ch >> 4, c = ch & 15;
        uint32_t a = swzo(r, c);
        size_t go = (size_t)ch * 16;
        CP16(tb + P_KH + a, gkh + go);
        CP16(tb + P_KL + a, gkl + go);
        CP16(tb + P_VH + a, gvh + go);
        CP16(tb + P_VL + a, gvl + go);
    }
    if (tid < 16) {
        CP16(sb + OFF_CE(b) + tid * 16,
             (const char*)(d_ce + bh * T_ + kt * BN) + tid * 16);
    } else if (tid < 32) {
        CP16(sb + OFF_G(b) + (tid - 16) * 16,
             (const char*)(d_g + bh * T_ + kt * BN) + (tid - 16) * 16);
    }
}

// ---------------------------------------------------------------------------
// Main kernel: 256 threads (8 warps), BM=128, BN=64, persistent queue,
// chain-major MMA ordering (same-accumulator distance = 8).
// ---------------------------------------------------------------------------
__global__ void __launch_bounds__(256, 1)
mlstm_mma(const float* __restrict__ q, float* __restrict__ out) {
    extern __shared__ char smem[];
    __shared__ int sh_task;
    const uint32_t sb = smem_u32(smem);
    const int tid  = threadIdx.x;
    const int lane = tid & 31;
    const int wid  = tid >> 5;
    const int m0   = wid * 16;
    const float scale = 0.08838834764831845f; // 128^-0.5

    int task = blockIdx.x;
    for (;;) {
        if (task >= NTASK) return;
        const int bh = task & 15;
        const int qt = (NQT - 1) - (task >> 4);    // descending work
        const int NT = 2 * qt + 2;
        const int q0 = qt * 128;

        // kick tile 0 fetch first, then stage Q planes (disjoint smem)
        load_tile(sb, 0, bh, 0, tid);
        CP_COMMIT();

        const float* qbase = q + (size_t)(bh * T_ + q0) * KD;
#pragma unroll
        for (int u = 0; u < 8; u++) {
            int ch = tid + u * 256;            // 0..2047
            int r = ch >> 4, c = ch & 15;
            const float4* src = (const float4*)(qbase + r * 128 + c * 8);
            float4 x0 = src[0], x1 = src[1];
            uint32_t h0, l0, h1, l1, h2, l2, h3, l3;
            split2f(x0.x * scale, x0.y * scale, h0, l0);
            split2f(x0.z * scale, x0.w * scale, h1, l1);
            split2f(x1.x * scale, x1.y * scale, h2, l2);
            split2f(x1.z * scale, x1.w * scale, h3, l3);
            uint32_t a = swzo(r, c);
            *(uint4*)(smem + OFF_QH + a) = make_uint4(h0, h1, h2, h3);
            *(uint4*)(smem + OFF_QL + a) = make_uint4(l0, l1, l2, l3);
        }

        const int rowg0 = q0 + m0 + (lane >> 2);
        const int rowg1 = rowg0 + 8;
        const float cm0 = d_cm[bh * T_ + rowg0];
        const float cm1 = d_cm[bh * T_ + rowg1];
        const float nf0 = d_nf[bh * T_ + rowg0];
        const float nf1 = d_nf[bh * T_ + rowg1];

        float hacc[16][4];
#pragma unroll
        for (int i = 0; i < 16; i++)
#pragma unroll
            for (int j = 0; j < 4; j++) hacc[i][j] = 0.f;
        float rs0 = 0.f, rs1 = 0.f;

        CP_WAIT0();
        __syncthreads();          // Q planes + tile 0 + aux 0 all visible

        for (int kt = 0; kt < NT; kt++) {
            const int b = kt & 1;
            if (kt + 1 < NT) { load_tile(sb, 1 - b, bh, kt + 1, tid); CP_COMMIT(); }
            const uint32_t tb = sb + OFF_TILE(b);
            const float Gtv = __ldg(&d_Gt[bh * NKT + kt]);

            const int  smin = kt * BN;
            const int  wmrow = q0 + m0;
            const bool fullmask = (smin > wmrow + 15);
            const bool partial  = !fullmask && (smin + BN - 1 > wmrow);

            if (!fullmask) {
                // ================= MMA1: S = Qs.K^T, distance-8 chains ======
                float sa[8][4];
#pragma unroll
                for (int i = 0; i < 8; i++)
#pragma unroll
                    for (int j = 0; j < 4; j++) sa[i][j] = 0.f;

#pragma unroll
                for (int kb = 0; kb < 8; kb++) {
                    uint32_t qhf[4], qlf[4];
                    {
                        int row = m0 + (lane & 15);
                        int ck  = 2 * kb + (lane >> 4);
                        ldm_x4(qhf, sb + OFF_QH + swzo(row, ck));
                        ldm_x4(qlf, sb + OFF_QL + swzo(row, ck));
                    }
                    uint32_t bhf[4][4], blf[4][4];
#pragma unroll
                    for (int np = 0; np < 4; np++) {
                        int row = 16 * np + (lane & 7) + ((lane >> 4) << 3);
                        int ck  = 2 * kb + ((lane >> 3) & 1);
                        ldm_x4(bhf[np], tb + P_KH + swzo(row, ck));
                        ldm_x4(blf[np], tb + P_KL + swzo(row, ck));
                    }
                    // chain qh x kh over 8 targets
#pragma unroll
                    for (int np = 0; np < 4; np++) {
                        mma16816(sa[2*np],   qhf, bhf[np][0], bhf[np][1]);
                        mma16816(sa[2*np+1], qhf, bhf[np][2], bhf[np][3]);
                    }
                    // chain ql x kh
#pragma unroll
                    for (int np = 0; np < 4; np++) {
                        mma16816(sa[2*np],   qlf, bhf[np][0], bhf[np][1]);
                        mma16816(sa[2*np+1], qlf, bhf[np][2], bhf[np][3]);
                    }
                    // chain qh x kl
#pragma unroll
                    for (int np = 0; np < 4; np++) {
                        mma16816(sa[2*np],   qhf, blf[np][0], blf[np][1]);
                        mma16816(sa[2*np+1], qhf, blf[np][2], blf[np][3]);
                    }
                }

                // ================= epilogue =================================
                const float* ce = (const float*)(smem + OFF_CE(b));
                const float* gg = (const float*)(smem + OFF_G(b));
                const float rr0 = __expf(Gtv - cm0);
                const float rr1 = __expf(Gtv - cm1);
                uint32_t phf[4][4], plf[4][4];
#pragma unroll
                for (int nb = 0; nb < 8; nb++) {
                    int n0 = 8 * nb + 2 * (lane & 3);
                    float p0, p1, p2, p3;
                    if (!partial) {
                        float c0 = ce[n0], c1 = ce[n0 + 1];
                        p0 = sa[nb][0] * rr0 * c0; p1 = sa[nb][1] * rr0 * c1;
                        p2 = sa[nb][2] * rr1 * c0; p3 = sa[nb][3] * rr1 * c1;
                    } else {
                        int s0g = smin + n0;
                        float g0 = gg[n0], g1 = gg[n0 + 1];
                        p0 = (s0g     <= rowg0) ? sa[nb][0] * __expf(g0 - cm0) : 0.f;
                        p1 = (s0g + 1 <= rowg0) ? sa[nb][1] * __expf(g1 - cm0) : 0.f;
                        p2 = (s0g     <= rowg1) ? sa[nb][2] * __expf(g0 - cm1) : 0.f;
                        p3 = (s0g + 1 <= rowg1) ? sa[nb][3] * __expf(g1 - cm1) : 0.f;
                    }
                    rs0 += p0 + p1; rs1 += p2 + p3;
                    int kf = nb >> 1, hx = (nb & 1) * 2;
                    split2f(p0, p1, phf[kf][hx],     plf[kf][hx]);
                    split2f(p2, p3, phf[kf][hx + 1], plf[kf][hx + 1]);
                }

                // ================= MMA2: H += P.V, distance-8 chains ========
#pragma unroll
                for (int kf = 0; kf < 4; kf++) {
#pragma unroll
                    for (int grp = 0; grp < 2; grp++) {
                        uint32_t vhf[4][4], vlf[4][4];
#pragma unroll
                        for (int j = 0; j < 4; j++) {
                            int np  = grp * 4 + j;
                            int row = 16 * kf + (lane & 7) + (((lane >> 3) & 1) << 3);
                            int ck  = 2 * np + (lane >> 4);
                            ldm_x4_t(vhf[j], tb + P_VH + swzo(row, ck));
                            ldm_x4_t(vlf[j], tb + P_VL + swzo(row, ck));
                        }
                        // chain ph x vh over 8 targets
#pragma unroll
                        for (int j = 0; j < 4; j++) {
                            int t = 8 * grp + 2 * j;
                            mma16816(hacc[t],   phf[kf], vhf[j][0], vhf[j][1]);
                            mma16816(hacc[t+1], phf[kf], vhf[j][2], vhf[j][3]);
                        }
                        // chain ph x vl
#pragma unroll
                        for (int j = 0; j < 4; j++) {
                            int t = 8 * grp + 2 * j;
                            mma16816(hacc[t],   phf[kf], vlf[j][0], vlf[j][1]);
                            mma16816(hacc[t+1], phf[kf], vlf[j][2], vlf[j][3]);
                        }
                        // chain pl x vh
#pragma unroll
                        for (int j = 0; j < 4; j++) {
                            int t = 8 * grp + 2 * j;
                            mma16816(hacc[t],   plf[kf], vhf[j][0], vhf[j][1]);
                            mma16816(hacc[t+1], plf[kf], vhf[j][2], vhf[j][3]);
                        }
                    }
                }
            }

            CP_WAIT0();
            __syncthreads();
        }

        // ---- reduce rowsums, normalize, write ----
        rs0 += __shfl_xor_sync(0xffffffffu, rs0, 1);
        rs0 += __shfl_xor_sync(0xffffffffu, rs0, 2);
        rs1 += __shfl_xor_sync(0xffffffffu, rs1, 1);
        rs1 += __shfl_xor_sync(0xffffffffu, rs1, 2);
        const float inv0 = 1.f / fmaxf(fabsf(rs0), nf0);
        const float inv1 = 1.f / fmaxf(fabsf(rs1), nf1);
        float* o0 = out + ((size_t)(bh * T_ + rowg0)) * KD;
        float* o1 = out + ((size_t)(bh * T_ + rowg1)) * KD;
#pragma unroll
        for (int nb = 0; nb < 16; nb++) {
            int c = 8 * nb + 2 * (lane & 3);
            *(float2*)(o0 + c) = make_float2(hacc[nb][0] * inv0, hacc[nb][1] * inv0);
            *(float2*)(o1 + c) = make_float2(hacc[nb][2] * inv1, hacc[nb][3] * inv1);
        }

        // ---- next task ----
        __syncthreads();
        if (tid == 0) sh_task = (int)atomicAdd(&d_task_ctr, 1u);
        __syncthreads();
        task = sh_task;
    }
}

// ---------------------------------------------------------------------------
extern "C" void kernel_launch(void* const* d_in, const int* in_sizes, int n_in,
                              void* d_out, int out_size) {
    const float* q  = (const float*)d_in[0];
    const float* k  = (const float*)d_in[1];
    const float* v  = (const float*)d_in[2];
    const float* ig = (const float*)d_in[3];
    const float* fg = (const float*)d_in[4];
    float* out = (float*)d_out;

    fused_pre<<<4096 + 16, 256>>>(k, v, ig, fg);

    cudaFuncSetAttribute(mlstm_mma,
                         cudaFuncAttributeMaxDynamicSharedMemorySize, SMEM_TOTAL);
    mlstm_mma<<<GRID_MAIN, 256, SMEM_TOTAL>>>(q, out);
}